// round 10
// baseline (speedup 1.0000x reference)
#include <cuda_runtime.h>
#include <cstdint>
#include <cstddef>

#define DI __device__ __forceinline__

// ---------------- problem constants ----------------
namespace {
constexpr int BN    = 128;
constexpr int CINc  = 64;
constexpr int NFc   = 16;
constexpr int COUTc = 256;
constexpr int Hc    = 20;
constexpr int Wc    = 20;
constexpr int HWc   = Hc * Wc;          // 400
constexpr int Kc    = CINc * NFc;       // 1024
constexpr int PP    = 21;               // padded spatial extent (index 20 == zero slot)
constexpr int PLANE = PP * PP * BN;     // floats per cin plane (56448)

constexpr int KCHUNK  = 32;
constexpr int NCHUNKS = Kc / KCHUNK;    // 32

// fused-kernel smem (words): A0 A1 | B0 B1 | G (tap gather buffer)
constexpr int A_WORDS = 4096;           // 128 rows x 32 k (frag layout)
constexpr int B_WORDS = 8192;           // 256 o  x 32 k (frag layout)
constexpr int GS      = 136;            // G k-stride: 136 = 8 mod 32 -> conflict-free
constexpr int G_TAP   = KCHUNK * GS;    // 4352 words per tap
constexpr int G_WORDS = 4 * G_TAP;      // 17408
constexpr int OFF_A0 = 0;
constexpr int OFF_A1 = OFF_A0 + A_WORDS;
constexpr int OFF_B0 = OFF_A1 + A_WORDS;
constexpr int OFF_B1 = OFF_B0 + B_WORDS;
constexpr int OFF_G  = OFF_B1 + B_WORDS;        // 24576
constexpr int SMEM_BYTES = (OFF_G + G_WORDS) * 4;   // 167936 B

struct Tap { int4 off; float4 w; };
}

// ---------------- device scratch (no allocations allowed) ----------------
__device__ float    d_xt[(size_t)CINc * PLANE];          // 14.5 MB
__device__ float    d_g[(size_t)BN * HWc * COUTc];       // 52.4 MB, [b][hw][o]
__device__ Tap      d_taps[HWc * NFc];                   // 200 KB
__device__ uint32_t d_comb_p[COUTc * Kc];                // 1 MB, frag-layout tf32
// comb frag layout: [gn(16 o-groups)][kc(32)][ks(4)] -> 512B block of
//   word = lq*16 + lc*4 + {0:(o lq,  k lc), 1:(o lq,  k lc+4),
//                          2:(o lq+8,k lc), 3:(o lq+8,k lc+4)}

// ---------------- small asm helpers ----------------
DI uint32_t smem_u32(const void* p) {
    uint32_t a;
    asm("{ .reg .u64 t; cvta.to.shared.u64 t, %1; cvt.u32.u64 %0, t; }"
        : "=r"(a) : "l"(p));
    return a;
}

DI uint32_t f2tf32(float f) {
    uint32_t u;
    asm("cvt.rna.tf32.f32 %0, %1;" : "=r"(u) : "f"(f));
    return u;
}

DI void cp_async16(uint32_t saddr, const void* gptr) {
    asm volatile("cp.async.cg.shared.global [%0], [%1], 16;"
                 :: "r"(saddr), "l"(gptr));
}
DI void cp_commit() { asm volatile("cp.async.commit_group;" ::: "memory"); }
template <int N>
DI void cp_wait() { asm volatile("cp.async.wait_group %0;" :: "n"(N) : "memory"); }

// m16n8k8 tf32 MMA, fp32 accumulate
DI void mma_tf32(float d[4], const uint32_t a[4], uint32_t b0, uint32_t b1) {
    asm volatile(
        "mma.sync.aligned.m16n8k8.row.col.f32.tf32.tf32.f32 "
        "{%0,%1,%2,%3}, {%4,%5,%6,%7}, {%8,%9}, {%0,%1,%2,%3};"
        : "+f"(d[0]), "+f"(d[1]), "+f"(d[2]), "+f"(d[3])
        : "r"(a[0]), "r"(a[1]), "r"(a[2]), "r"(a[3]), "r"(b0), "r"(b1));
}

// ---------------- kernel 1: x (B,CIN,H,W) -> xt[cin][21][21][b] ----------------
__global__ void __launch_bounds__(256) xt_kernel(const float* __restrict__ x) {
    __shared__ float tile[BN * PP];
    const int cin = blockIdx.x;
    const int i   = blockIdx.y;       // 0..20
    const int tid = threadIdx.x;
    float* dst = d_xt + (size_t)cin * PLANE + (size_t)i * PP * BN;

    if (i == Hc) {
        for (int p = tid; p < PP * BN; p += 256) dst[p] = 0.0f;
        return;
    }
    for (int p = tid; p < BN * Wc; p += 256) {
        int b = p / Wc, j = p % Wc;
        tile[b * PP + j] = x[(((size_t)b * CINc + cin) * Hc + i) * Wc + j];
    }
    __syncthreads();
    for (int p = tid; p < PP * BN; p += 256) {
        int j = p / BN, b = p % BN;
        dst[(size_t)j * BN + b] = (j < Wc) ? tile[b * PP + j] : 0.0f;
    }
}

// ---------------- kernel 2: tap table -----------------------------------------
__global__ void __launch_bounds__(256) taps_kernel(const float* __restrict__ flow) {
    int id = blockIdx.x * 256 + threadIdx.x;
    if (id >= HWc * NFc) return;
    int hw = id / NFc, nf = id % NFc;
    int h = hw / Wc, w = hw % Wc;

    float f0 = flow[(((size_t)nf * Hc + h) * Wc + w) * 2 + 0];
    float f1 = flow[(((size_t)nf * Hc + h) * Wc + w) * 2 + 1];
    float ix = (float)h + f0;
    float iy = (float)w + f1;
    float bx = floorf(ix), by = floorf(iy);
    float s = ix - bx, t = iy - by;
    int ibx = (int)bx, iby = (int)by;

    int px0 = min(max(ibx,     0), Hc);
    int px1 = min(max(ibx + 1, 0), Hc);
    int py0 = min(max(iby,     0), Wc);
    int py1 = min(max(iby + 1, 0), Wc);

    Tap tp;
    tp.off = make_int4((px0 * PP + py0) * BN,
                       (px1 * PP + py0) * BN,
                       (px0 * PP + py1) * BN,
                       (px1 * PP + py1) * BN);
    float w01 = s * (1.0f - t);   // NOTE: also used for the (bx, by+1) tap (source bug)
    tp.w = make_float4((1.0f - s) * (1.0f - t), w01, w01, s * t);
    d_taps[hw * NFc + nf] = tp;
}

// ---------------- kernel 3: comb -> tf32 in frag layout ------------------------
__global__ void __launch_bounds__(256) combp_kernel(const float* __restrict__ comb) {
    int idx = blockIdx.x * 256 + threadIdx.x;       // word index
    if (idx >= COUTc * Kc) return;
    int gn = idx >> 14;          // 16 o-groups (16384 words each)
    int r  = idx & 16383;
    int kc = r >> 9;             // 32
    int r2 = r & 511;
    int ks = r2 >> 7;            // 4
    int r3 = r2 & 127;
    int lq = r3 >> 4;
    int r4 = r3 & 15;
    int lc = r4 >> 2;
    int w  = r4 & 3;
    int o  = gn * 16 + lq + ((w >= 2) ? 8 : 0);
    int k  = kc * KCHUNK + ks * 8 + lc + ((w & 1) ? 4 : 0);
    d_comb_p[idx] = f2tf32(comb[(size_t)o * Kc + k]);
}

// ---------------- kernel 4: FUSED gather(cp.async) + tf32 GEMM -----------------
// One CTA per pixel hw. 512 threads = 16 warps, warp grid 4(M) x 4(N),
// warp tile 32x64. Raw tap rows land in smem G via cp.async (no registers);
// pass2 does the 4-tap weighted reduction G -> A frag buffer.
__global__ void __launch_bounds__(512, 1) gemm_kernel() {
    extern __shared__ uint32_t smem[];
    __shared__ Tap taps_sm[NFc];

    const int hw   = blockIdx.x;
    const int tid  = threadIdx.x;
    const int lane = tid & 31;
    const int wid  = tid >> 5;
    const int wm   = wid >> 2;            // 0..3 (M)
    const int wn   = wid & 3;             // 0..3 (N)
    const int lq   = lane >> 2;
    const int lc   = lane & 3;

    if (tid < NFc) taps_sm[tid] = d_taps[hw * NFc + tid];
    __syncthreads();

    const uint32_t sbase = smem_u32(smem);
    float* G = reinterpret_cast<float*>(smem + OFF_G);

    // ---- per-thread precomputed gather/B-load addresses (chunk-independent) ----
    uint32_t gdst[8];       // smem byte addresses into G
    int32_t  gsrc[8];       // word offsets into d_xt (+ kc*2*PLANE per chunk)
    #pragma unroll
    for (int i = 0; i < 8; ++i) {
        const int u   = tid + i * 512;    // 0..4095
        const int tap = u >> 10;          // 0..3
        const int k   = (u >> 5) & 31;    // 0..31
        const int seg = u & 31;           // 16B segment over b
        const int off = (&taps_sm[k & 15].off.x)[tap];
        gsrc[i] = (k >> 4) * PLANE + off + seg * 4;
        gdst[i] = sbase + (uint32_t)(OFF_G + tap * G_TAP + k * GS + seg * 4) * 4;
    }
    uint32_t bdst[4];       // byte offsets within a B buffer
    int32_t  bsrc[4];       // word offsets into d_comb_p (+ kc*512 per chunk)
    #pragma unroll
    for (int i = 0; i < 4; ++i) {
        const int unit  = tid + i * 512;  // 0..2047
        const int gb    = unit >> 7;
        const int inner = unit & 127;
        bsrc[i] = gb * (NCHUNKS * 512) + inner * 4;
        bdst[i] = (uint32_t)(gb * 512 + inner * 4) * 4;
    }

    auto issueG = [&](int kc) {
        const float* base = d_xt + (size_t)kc * 2 * PLANE;
        #pragma unroll
        for (int i = 0; i < 8; ++i) cp_async16(gdst[i], base + gsrc[i]);
    };
    auto issueB = [&](int kc, int boff) {
        const uint32_t* base = d_comb_p + (size_t)kc * 512;
        const uint32_t d0 = sbase + (uint32_t)boff * 4;
        #pragma unroll
        for (int i = 0; i < 4; ++i) cp_async16(d0 + bdst[i], base + bsrc[i]);
    };

    // ---- pass2: G -> A frag buffer (weighted 4-tap reduction) ----
    const int p2gi  = tid >> 6;
    const int p2ks2 = (tid >> 5) & 1;
    const int p2lq  = (tid & 31) >> 2;
    const int p2lc  = tid & 3;
    const int p2br  = p2gi * 16 + p2lq;
    auto gval = [&](int k, int b, const float4& w) -> float {
        const int a = k * GS + b;
        return G[a] * w.x + G[G_TAP + a] * w.y
             + G[2 * G_TAP + a] * w.z + G[3 * G_TAP + a] * w.w;
    };
    auto pass2 = [&](uint32_t* Ab) {
        #pragma unroll
        for (int j = 0; j < 2; ++j) {
            const int ks = p2ks2 * 2 + j;
            const int k0 = ks * 8 + p2lc;
            const int k1 = k0 + 4;
            const float4 w0 = taps_sm[k0 & 15].w;
            const float4 w1 = taps_sm[k1 & 15].w;
            uint4 pk;
            pk.x = f2tf32(gval(k0, p2br,     w0));
            pk.y = f2tf32(gval(k1, p2br,     w1));
            pk.z = f2tf32(gval(k0, p2br + 8, w0));
            pk.w = f2tf32(gval(k1, p2br + 8, w1));
            *reinterpret_cast<uint4*>(Ab + (p2gi * 4 + ks) * 128 + p2lq * 16 + p2lc * 4) = pk;
        }
    };

    float acc[2][8][4];
    #pragma unroll
    for (int mi = 0; mi < 2; ++mi)
        #pragma unroll
        for (int nj = 0; nj < 8; ++nj)
            #pragma unroll
            for (int e = 0; e < 4; ++e) acc[mi][nj][e] = 0.0f;

    auto mma_ks = [&](const uint32_t* A, const uint32_t* B, int ks) {
        uint32_t a[2][4];
        #pragma unroll
        for (int mi = 0; mi < 2; ++mi) {
            const int gi = wm * 2 + mi;
            uint4 v = *reinterpret_cast<const uint4*>(
                A + (gi * 4 + ks) * 128 + lq * 16 + lc * 4);
            a[mi][0] = v.x; a[mi][1] = v.z; a[mi][2] = v.y; a[mi][3] = v.w;
        }
        #pragma unroll
        for (int p2 = 0; p2 < 4; ++p2) {
            const int gb = wn * 4 + p2;
            uint4 bv = *reinterpret_cast<const uint4*>(
                B + (gb * 4 + ks) * 128 + lq * 16 + lc * 4);
            #pragma unroll
            for (int mi = 0; mi < 2; ++mi) {
                mma_tf32(acc[mi][p2 * 2 + 0], a[mi], bv.x, bv.y);
                mma_tf32(acc[mi][p2 * 2 + 1], a[mi], bv.z, bv.w);
            }
        }
    };

    // ---- prologue: chunk 0 ----
    issueG(0); issueB(0, OFF_B0); cp_commit();
    cp_wait<0>();
    __syncthreads();            // G(0)/B0 visible
    pass2(smem + OFF_A0);
    __syncthreads();            // A0 ready, G free

    #pragma unroll 2
    for (int c = 0; c < NCHUNKS; ++c) {
        const int p = c & 1;
        const bool more = (c + 1 < NCHUNKS);
        const uint32_t* A = smem + (p ? OFF_A1 : OFF_A0);
        const uint32_t* B = smem + (p ? OFF_B1 : OFF_B0);

        if (more) {
            issueG(c + 1);
            issueB(c + 1, p ? OFF_B0 : OFF_B1);
            cp_commit();
        }
        mma_ks(A, B, 0);
        mma_ks(A, B, 1);
        mma_ks(A, B, 2);
        mma_ks(A, B, 3);
        if (more) {
            cp_wait<0>();
            __syncthreads();    // G(c+1)/B(c+1) visible; A/B[p] fully consumed
            pass2(smem + (p ? OFF_A0 : OFF_A1));
            __syncthreads();    // A[q] ready, G free
        }
    }

    // ---- writeback to d_g[b][hw][o] ----
    #pragma unroll
    for (int mi = 0; mi < 2; ++mi) {
        const int r0 = wm * 32 + mi * 16 + lq;        // b
        #pragma unroll
        for (int nj = 0; nj < 8; ++nj) {
            const int o = (wn * 4 + (nj >> 1)) * 16 + (nj & 1) * 8 + 2 * lc;
            *reinterpret_cast<float2*>(&d_g[((size_t)r0 * HWc + hw) * COUTc + o]) =
                make_float2(acc[mi][nj][0], acc[mi][nj][1]);
            *reinterpret_cast<float2*>(&d_g[((size_t)(r0 + 8) * HWc + hw) * COUTc + o]) =
                make_float2(acc[mi][nj][2], acc[mi][nj][3]);
        }
    }
}

// ---------------- kernel 5: g[b][hw][o] -> out[b][o][hw] + bias (float4) -------
__global__ void __launch_bounds__(256) trans_kernel(const float* __restrict__ bias,
                                                    float* __restrict__ out) {
    __shared__ float tile[32][33];
    const int tid = threadIdx.x;       // 0..255 (flat block)
    const int ht  = blockIdx.x;        // 13
    const int ot  = blockIdx.y;        // 8
    const int b   = blockIdx.z;        // 128

    {
        const int hw_l = tid >> 3;
        const int o4   = tid & 7;
        const int hw   = ht * 32 + hw_l;
        if (hw < HWc) {
            float4 v = *reinterpret_cast<const float4*>(
                &d_g[((size_t)b * HWc + hw) * COUTc + ot * 32 + o4 * 4]);
            tile[hw_l][o4 * 4 + 0] = v.x;
            tile[hw_l][o4 * 4 + 1] = v.y;
            tile[hw_l][o4 * 4 + 2] = v.z;
            tile[hw_l][o4 * 4 + 3] = v.w;
        }
    }
    __syncthreads();
    {
        const int o_l = tid >> 3;
        const int hw4 = tid & 7;
        const int hw0 = ht * 32 + hw4 * 4;
        if (hw0 < HWc) {
            const int o = ot * 32 + o_l;
            const float bv = bias[o];
            float4 v;
            v.x = tile[hw4 * 4 + 0][o_l] + bv;
            v.y = tile[hw4 * 4 + 1][o_l] + bv;
            v.z = tile[hw4 * 4 + 2][o_l] + bv;
            v.w = tile[hw4 * 4 + 3][o_l] + bv;
            *reinterpret_cast<float4*>(&out[((size_t)b * COUTc + o) * HWc + hw0]) = v;
        }
    }
}

// ---------------- launch ----------------
extern "C" void kernel_launch(void* const* d_in, const int* in_sizes, int n_in,
                              void* d_out, int out_size) {
    const float* x    = (const float*)d_in[0];   // (128, 64, 20, 20)
    const float* flow = (const float*)d_in[1];   // (16, 20, 20, 2)
    const float* comb = (const float*)d_in[2];   // (256, 1024)
    const float* bias = (const float*)d_in[3];   // (256,)
    float* out = (float*)d_out;                  // (128, 256, 20, 20)

    cudaFuncSetAttribute(gemm_kernel,
                         cudaFuncAttributeMaxDynamicSharedMemorySize, SMEM_BYTES);

    xt_kernel<<<dim3(CINc, PP), 256>>>(x);
    taps_kernel<<<(HWc * NFc + 255) / 256, 256>>>(flow);
    combp_kernel<<<(COUTc * Kc + 255) / 256, 256>>>(comb);
    gemm_kernel<<<HWc, 512, SMEM_BYTES>>>();
    trans_kernel<<<dim3(13, 8, BN), 256>>>(bias, out);
}

// round 12
// speedup vs baseline: 1.1340x; 1.1340x over previous
#include <cuda_runtime.h>
#include <cstdint>
#include <cstddef>

#define DI __device__ __forceinline__

// ---------------- problem constants ----------------
namespace {
constexpr int BN    = 128;
constexpr int CINc  = 64;
constexpr int NFc   = 16;
constexpr int COUTc = 256;
constexpr int Hc    = 20;
constexpr int Wc    = 20;
constexpr int HWc   = Hc * Wc;          // 400
constexpr int Kc    = CINc * NFc;       // 1024
constexpr int PP    = 21;               // padded spatial extent (index 20 == zero slot)
constexpr int PLANE = PP * PP * BN;     // floats per cin plane (56448)

constexpr int KCHUNK  = 32;
constexpr int NCHUNKS = Kc / KCHUNK;    // 32

// fused-kernel smem (words): tile M=64 x N=256
constexpr int A_WORDS = 2048;           // 64 rows x 32 k (frag layout, 4 groups)
constexpr int B_WORDS = 8192;           // 256 o x 32 k (frag layout, 16 groups)
constexpr int SB_S    = 72;             // sbuf k-stride (72 mod 32 = 8 -> conflict-free)
constexpr int SBUF_WORDS = KCHUNK * SB_S;   // 2304
constexpr int OFF_A0 = 0;
constexpr int OFF_A1 = OFF_A0 + A_WORDS;    // 2048
constexpr int OFF_B0 = OFF_A1 + A_WORDS;    // 4096
constexpr int OFF_B1 = OFF_B0 + B_WORDS;    // 12288
constexpr int OFF_SBUF = OFF_B1 + B_WORDS;  // 20480
constexpr int SMEM_BYTES = (OFF_SBUF + SBUF_WORDS) * 4;   // 91136 B -> 2 CTAs/SM

struct Tap { int4 off; float4 w; };
}

// ---------------- device scratch (no allocations allowed) ----------------
__device__ float    d_xt[(size_t)CINc * PLANE];          // 14.5 MB
__device__ float    d_g[(size_t)BN * HWc * COUTc];       // 52.4 MB, [b][hw][o]
__device__ Tap      d_taps[HWc * NFc];                   // 200 KB
__device__ uint32_t d_comb_p[COUTc * Kc];                // 1 MB, frag-layout tf32
// comb frag layout: [gn(16 o-groups)][kc(32)][ks(4)] -> 512B block of
//   word = lq*16 + lc*4 + {0:(o lq,  k lc), 1:(o lq,  k lc+4),
//                          2:(o lq+8,k lc), 3:(o lq+8,k lc+4)}

// ---------------- small asm helpers ----------------
DI uint32_t smem_u32(const void* p) {
    uint32_t a;
    asm("{ .reg .u64 t; cvta.to.shared.u64 t, %1; cvt.u32.u64 %0, t; }"
        : "=r"(a) : "l"(p));
    return a;
}

DI uint32_t f2tf32(float f) {
    uint32_t u;
    asm("cvt.rna.tf32.f32 %0, %1;" : "=r"(u) : "f"(f));
    return u;
}

DI void cp_async16(uint32_t saddr, const void* gptr) {
    asm volatile("cp.async.cg.shared.global [%0], [%1], 16;"
                 :: "r"(saddr), "l"(gptr));
}
DI void cp_commit() { asm volatile("cp.async.commit_group;" ::: "memory"); }
template <int N>
DI void cp_wait() { asm volatile("cp.async.wait_group %0;" :: "n"(N) : "memory"); }

// m16n8k8 tf32 MMA, fp32 accumulate
DI void mma_tf32(float d[4], const uint32_t a[4], uint32_t b0, uint32_t b1) {
    asm volatile(
        "mma.sync.aligned.m16n8k8.row.col.f32.tf32.tf32.f32 "
        "{%0,%1,%2,%3}, {%4,%5,%6,%7}, {%8,%9}, {%0,%1,%2,%3};"
        : "+f"(d[0]), "+f"(d[1]), "+f"(d[2]), "+f"(d[3])
        : "r"(a[0]), "r"(a[1]), "r"(a[2]), "r"(a[3]), "r"(b0), "r"(b1));
}

// ---------------- kernel 1: x (B,CIN,H,W) -> xt[cin][21][21][b] ----------------
__global__ void __launch_bounds__(256) xt_kernel(const float* __restrict__ x) {
    __shared__ float tile[BN * PP];
    const int cin = blockIdx.x;
    const int i   = blockIdx.y;       // 0..20
    const int tid = threadIdx.x;
    float* dst = d_xt + (size_t)cin * PLANE + (size_t)i * PP * BN;

    if (i == Hc) {
        for (int p = tid; p < PP * BN; p += 256) dst[p] = 0.0f;
        return;
    }
    for (int p = tid; p < BN * Wc; p += 256) {
        int b = p / Wc, j = p % Wc;
        tile[b * PP + j] = x[(((size_t)b * CINc + cin) * Hc + i) * Wc + j];
    }
    __syncthreads();
    for (int p = tid; p < PP * BN; p += 256) {
        int j = p / BN, b = p % BN;
        dst[(size_t)j * BN + b] = (j < Wc) ? tile[b * PP + j] : 0.0f;
    }
}

// ---------------- kernel 2: tap table -----------------------------------------
__global__ void __launch_bounds__(256) taps_kernel(const float* __restrict__ flow) {
    int id = blockIdx.x * 256 + threadIdx.x;
    if (id >= HWc * NFc) return;
    int hw = id / NFc, nf = id % NFc;
    int h = hw / Wc, w = hw % Wc;

    float f0 = flow[(((size_t)nf * Hc + h) * Wc + w) * 2 + 0];
    float f1 = flow[(((size_t)nf * Hc + h) * Wc + w) * 2 + 1];
    float ix = (float)h + f0;
    float iy = (float)w + f1;
    float bx = floorf(ix), by = floorf(iy);
    float s = ix - bx, t = iy - by;
    int ibx = (int)bx, iby = (int)by;

    int px0 = min(max(ibx,     0), Hc);
    int px1 = min(max(ibx + 1, 0), Hc);
    int py0 = min(max(iby,     0), Wc);
    int py1 = min(max(iby + 1, 0), Wc);

    Tap tp;
    tp.off = make_int4((px0 * PP + py0) * BN,
                       (px1 * PP + py0) * BN,
                       (px0 * PP + py1) * BN,
                       (px1 * PP + py1) * BN);
    float w01 = s * (1.0f - t);   // NOTE: also used for the (bx, by+1) tap (source bug)
    tp.w = make_float4((1.0f - s) * (1.0f - t), w01, w01, s * t);
    d_taps[hw * NFc + nf] = tp;
}

// ---------------- kernel 3: comb -> tf32 in frag layout ------------------------
__global__ void __launch_bounds__(256) combp_kernel(const float* __restrict__ comb) {
    int idx = blockIdx.x * 256 + threadIdx.x;       // word index
    if (idx >= COUTc * Kc) return;
    int gn = idx >> 14;          // 16 o-groups (16384 words each)
    int r  = idx & 16383;
    int kc = r >> 9;             // 32
    int r2 = r & 511;
    int ks = r2 >> 7;            // 4
    int r3 = r2 & 127;
    int lq = r3 >> 4;
    int r4 = r3 & 15;
    int lc = r4 >> 2;
    int w  = r4 & 3;
    int o  = gn * 16 + lq + ((w >= 2) ? 8 : 0);
    int k  = kc * KCHUNK + ks * 8 + lc + ((w & 1) ? 4 : 0);
    d_comb_p[idx] = f2tf32(comb[(size_t)o * Kc + k]);
}

// ---------------- kernel 4: FUSED gather + tf32 GEMM, 2 CTAs/SM ----------------
// Grid (2 b-halves, 400 hw). 256 threads = 8 warps: 2(M) x 4(N), warp 32x64.
// Tile M=64 (b = mh*64..), N=256, K in 32 chunks. Two CTAs co-reside per SM so
// one CTA's barriers/pass2 hide under the other's MMA stream.
__global__ void __launch_bounds__(256, 2) gemm_kernel() {
    extern __shared__ uint32_t smem[];
    __shared__ Tap taps_sm[NFc];

    const int mh   = blockIdx.x;          // b-half, fast axis
    const int hw   = blockIdx.y;
    const int tid  = threadIdx.x;
    const int lane = tid & 31;
    const int wid  = tid >> 5;
    const int wm   = wid >> 2;            // 0..1 (M)
    const int wn   = wid & 3;             // 0..3 (N)
    const int lq   = lane >> 2;
    const int lc   = lane & 3;

    if (tid < NFc) taps_sm[tid] = d_taps[hw * NFc + tid];
    __syncthreads();

    const uint32_t sbase = smem_u32(smem);
    float* sbuf = reinterpret_cast<float*>(smem + OFF_SBUF);
    const int bbase = mh * 64;

    // ---- pass1 (gather, reduced): 512 units = 32 k x 16 b-segments; 2/thread --
    auto p1_load = [&](int kc, int which, float4 v[4], Tap& tp) {
        const int u   = tid + which * 256;
        const int k   = u >> 4;
        const int seg = u & 15;
        const int cin = kc * 2 + (k >> 4);
        tp = taps_sm[k & 15];
        const float* __restrict__ plane = d_xt + (size_t)cin * PLANE + bbase + seg * 4;
        v[0] = *reinterpret_cast<const float4*>(plane + tp.off.x);
        v[1] = *reinterpret_cast<const float4*>(plane + tp.off.y);
        v[2] = *reinterpret_cast<const float4*>(plane + tp.off.z);
        v[3] = *reinterpret_cast<const float4*>(plane + tp.off.w);
    };
    auto p1_store = [&](int which, const float4 v[4], const Tap& tp) {
        const int u   = tid + which * 256;
        const int k   = u >> 4;
        const int seg = u & 15;
        float4 r;
        r.x = v[0].x * tp.w.x + v[1].x * tp.w.y + v[2].x * tp.w.z + v[3].x * tp.w.w;
        r.y = v[0].y * tp.w.x + v[1].y * tp.w.y + v[2].y * tp.w.z + v[3].y * tp.w.w;
        r.z = v[0].z * tp.w.x + v[1].z * tp.w.y + v[2].z * tp.w.z + v[3].z * tp.w.w;
        r.w = v[0].w * tp.w.x + v[1].w * tp.w.y + v[2].w * tp.w.z + v[3].w * tp.w.w;
        *reinterpret_cast<float4*>(&sbuf[k * SB_S + seg * 4]) = r;
    };

    // ---- pass2: sbuf -> A frag buffer (8 words/thread) ----
    const int p2gi  = tid >> 6;            // 0..3 (16-row group)
    const int p2ks2 = (tid >> 5) & 1;
    const int p2lq  = (tid & 31) >> 2;
    const int p2lc  = tid & 3;
    const int p2br  = p2gi * 16 + p2lq;    // 0..63 local row
    auto pass2 = [&](uint32_t* Ab) {
        #pragma unroll
        for (int j = 0; j < 2; ++j) {
            const int ks = p2ks2 * 2 + j;
            const int k0 = ks * 8 + p2lc;
            const int k1 = k0 + 4;
            uint4 pk;
            pk.x = f2tf32(sbuf[k0 * SB_S + p2br]);
            pk.y = f2tf32(sbuf[k1 * SB_S + p2br]);
            pk.z = f2tf32(sbuf[k0 * SB_S + p2br + 8]);
            pk.w = f2tf32(sbuf[k1 * SB_S + p2br + 8]);
            *reinterpret_cast<uint4*>(Ab + (p2gi * 4 + ks) * 128 + p2lq * 16 + p2lc * 4) = pk;
        }
    };

    // ---- B load: comb chunk (32 KB), 8 x 16B per thread ----
    auto issueB = [&](int kc, int boff) {
        const uint32_t* base = d_comb_p + (size_t)kc * 512;
        #pragma unroll
        for (int i = 0; i < 8; ++i) {
            const int unit  = tid + i * 256;       // 0..2047
            const int gb    = unit >> 7;           // o-group 0..15
            const int inner = unit & 127;
            cp_async16(sbase + (uint32_t)(boff + gb * 512 + inner * 4) * 4,
                       base + (size_t)gb * (NCHUNKS * 512) + inner * 4);
        }
    };

    float acc[2][8][4];
    #pragma unroll
    for (int mi = 0; mi < 2; ++mi)
        #pragma unroll
        for (int nj = 0; nj < 8; ++nj)
            #pragma unroll
            for (int e = 0; e < 4; ++e) acc[mi][nj][e] = 0.0f;

    auto mma_ks = [&](const uint32_t* A, const uint32_t* B, int ks) {
        uint32_t a[2][4];
        #pragma unroll
        for (int mi = 0; mi < 2; ++mi) {
            const int gi = wm * 2 + mi;            // 0..3
            uint4 v = *reinterpret_cast<const uint4*>(
                A + (gi * 4 + ks) * 128 + lq * 16 + lc * 4);
            a[mi][0] = v.x; a[mi][1] = v.z; a[mi][2] = v.y; a[mi][3] = v.w;
        }
        #pragma unroll
        for (int p2 = 0; p2 < 4; ++p2) {
            const int gb = wn * 4 + p2;            // 0..15
            uint4 bv = *reinterpret_cast<const uint4*>(
                B + (gb * 4 + ks) * 128 + lq * 16 + lc * 4);
            #pragma unroll
            for (int mi = 0; mi < 2; ++mi) {
                mma_tf32(acc[mi][p2 * 2 + 0], a[mi], bv.x, bv.y);
                mma_tf32(acc[mi][p2 * 2 + 1], a[mi], bv.z, bv.w);
            }
        }
    };

    // ---- prologue: chunk 0 ----
    {
        float4 v[4]; Tap tp;
        p1_load(0, 0, v, tp); p1_store(0, v, tp);
        p1_load(0, 1, v, tp); p1_store(1, v, tp);
    }
    issueB(0, OFF_B0); cp_commit();
    __syncthreads();            // sbuf(0) visible
    pass2(smem + OFF_A0);
    cp_wait<0>();
    __syncthreads();            // A0/B0 ready; sbuf free

    for (int c = 0; c < NCHUNKS; ++c) {
        const int p = c & 1;
        const bool more = (c + 1 < NCHUNKS);
        const uint32_t* A = smem + (p ? OFF_A1 : OFF_A0);
        const uint32_t* B = smem + (p ? OFF_B1 : OFF_B0);

        if (more) { issueB(c + 1, p ? OFF_B0 : OFF_B1); cp_commit(); }

        float4 v[4]; Tap tp;
        if (more) p1_load(c + 1, 0, v, tp);       // LDGs in flight...
        mma_ks(A, B, 0);
        mma_ks(A, B, 1);                           // ...retire under MMA
        if (more) {
            p1_store(0, v, tp);
            p1_load(c + 1, 1, v, tp);
        }
        mma_ks(A, B, 2);
        mma_ks(A, B, 3);
        if (more) p1_store(1, v, tp);

        __syncthreads();        // sbuf(c+1) ready; A/B[p] consumed
        if (more) pass2(smem + (p ? OFF_A0 : OFF_A1));
        cp_wait<0>();           // B(c+1) landed during MMAs
        __syncthreads();        // A/B[q] ready; sbuf free
    }

    // ---- writeback to d_g[b][hw][o] ----
    #pragma unroll
    for (int mi = 0; mi < 2; ++mi) {
        const int r0 = bbase + wm * 32 + mi * 16 + lq;    // global b
        #pragma unroll
        for (int nj = 0; nj < 8; ++nj) {
            const int o = (wn * 4 + (nj >> 1)) * 16 + (nj & 1) * 8 + 2 * lc;
            *reinterpret_cast<float2*>(&d_g[((size_t)r0 * HWc + hw) * COUTc + o]) =
                make_float2(acc[mi][nj][0], acc[mi][nj][1]);
            *reinterpret_cast<float2*>(&d_g[((size_t)(r0 + 8) * HWc + hw) * COUTc + o]) =
                make_float2(acc[mi][nj][2], acc[mi][nj][3]);
        }
    }
}

// ---------------- kernel 5: g[b][hw][o] -> out[b][o][hw] + bias (float4) -------
__global__ void __launch_bounds__(256) trans_kernel(const float* __restrict__ bias,
                                                    float* __restrict__ out) {
    __shared__ float tile[32][33];
    const int tid = threadIdx.x;       // 0..255 (flat block)
    const int ht  = blockIdx.x;        // 13
    const int ot  = blockIdx.y;        // 8
    const int b   = blockIdx.z;        // 128

    {
        const int hw_l = tid >> 3;
        const int o4   = tid & 7;
        const int hw   = ht * 32 + hw_l;
        if (hw < HWc) {
            float4 v = *reinterpret_cast<const float4*>(
                &d_g[((size_t)b * HWc + hw) * COUTc + ot * 32 + o4 * 4]);
            tile[hw_l][o4 * 4 + 0] = v.x;
            tile[hw_l][o4 * 4 + 1] = v.y;
            tile[hw_l][o4 * 4 + 2] = v.z;
            tile[hw_l][o4 * 4 + 3] = v.w;
        }
    }
    __syncthreads();
    {
        const int o_l = tid >> 3;
        const int hw4 = tid & 7;
        const int hw0 = ht * 32 + hw4 * 4;
        if (hw0 < HWc) {
            const int o = ot * 32 + o_l;
            const float bv = bias[o];
            float4 v;
            v.x = tile[hw4 * 4 + 0][o_l] + bv;
            v.y = tile[hw4 * 4 + 1][o_l] + bv;
            v.z = tile[hw4 * 4 + 2][o_l] + bv;
            v.w = tile[hw4 * 4 + 3][o_l] + bv;
            *reinterpret_cast<float4*>(&out[((size_t)b * COUTc + o) * HWc + hw0]) = v;
        }
    }
}

// ---------------- launch ----------------
extern "C" void kernel_launch(void* const* d_in, const int* in_sizes, int n_in,
                              void* d_out, int out_size) {
    const float* x    = (const float*)d_in[0];   // (128, 64, 20, 20)
    const float* flow = (const float*)d_in[1];   // (16, 20, 20, 2)
    const float* comb = (const float*)d_in[2];   // (256, 1024)
    const float* bias = (const float*)d_in[3];   // (256,)
    float* out = (float*)d_out;                  // (128, 256, 20, 20)

    cudaFuncSetAttribute(gemm_kernel,
                         cudaFuncAttributeMaxDynamicSharedMemorySize, SMEM_BYTES);

    xt_kernel<<<dim3(CINc, PP), 256>>>(x);
    taps_kernel<<<(HWc * NFc + 255) / 256, 256>>>(flow);
    combp_kernel<<<(COUTc * Kc + 255) / 256, 256>>>(comb);
    gemm_kernel<<<dim3(2, HWc), 256, SMEM_BYTES>>>();
    trans_kernel<<<dim3(13, 8, BN), 256>>>(bias, out);
}